// round 4
// baseline (speedup 1.0000x reference)
#include <cuda_runtime.h>

// Problem constants
constexpr int B_TOT = 16384;
constexpr int F = 40;
constexpr int D = 32;
constexpr int NB = 8;                 // batches per CTA
constexpr int FD = F * D;             // 1280
constexpr int FF = F * F;             // 1600

// Shared layout (floats):
//  h_s / aggr_s : NB*FD  = 10240
//  hout_s       : NB*FD  = 10240
//  g_s (transp) : NB*FF  = 12800   layout [j][g][f]
constexpr int SMEM_FLOATS = NB * FD * 2 + NB * FF;   // 33280
constexpr int SMEM_BYTES = SMEM_FLOATS * 4;          // 133120

__global__ void __launch_bounds__(256, 1)
graphlayer_kernel(const float* __restrict__ g,
                  const float* __restrict__ h,
                  const float* __restrict__ W_in,
                  const float* __restrict__ W_out,
                  const float* __restrict__ bias_p,
                  float* __restrict__ out)
{
    extern __shared__ float smem[];
    float* h_s    = smem;                 // also reused for aggr after stage 2
    float* hout_s = smem + NB * FD;
    float* g_s    = smem + 2 * NB * FD;   // [j][g][f]

    const int tid  = threadIdx.x;
    const int lane = tid & 31;            // = d index
    const int warp = tid >> 5;            // 8 warps
    const long b0  = (long)blockIdx.x * NB;

    // ---------------- Stage 0: stage h (copy) and g (transpose) ----------------
    {
        const float4* hg4 = (const float4*)(h + b0 * FD);
        float4*       hs4 = (float4*)h_s;
        #pragma unroll
        for (int i = 0; i < (NB * FD / 4) / 256; i++) {     // 10 iters
            hs4[tid + i * 256] = hg4[tid + i * 256];
        }
        const float* gg = g + b0 * FF;
        #pragma unroll
        for (int i = 0; i < (NB * FF) / 256; i++) {         // 50 iters
            int idx = tid + i * 256;
            int j   = idx / FF;
            int r   = idx - j * FF;
            int f   = r / F;
            int gi  = r - f * F;
            g_s[j * FF + gi * F + f] = gg[idx];             // transpose write
        }
    }
    __syncthreads();

    // ---------------- Stage 1: hout[j][f][d] = sum_e W_out[f][d][e] * h[j][f][e] ----------------
    #pragma unroll
    for (int k = 0; k < 5; k++) {
        const int f = warp + k * 8;
        const float4* w4p = (const float4*)(W_out + (f * D + lane) * D);
        float acc[NB];
        #pragma unroll
        for (int j = 0; j < NB; j++) acc[j] = 0.0f;
        #pragma unroll
        for (int eq = 0; eq < D / 4; eq++) {                // 8 e-quads
            const float4 w = __ldg(w4p + eq);
            #pragma unroll
            for (int j = 0; j < NB; j++) {
                const float4 hv = *(const float4*)&h_s[j * FD + f * D + eq * 4];
                acc[j] += w.x * hv.x + w.y * hv.y + w.z * hv.z + w.w * hv.w;
            }
        }
        #pragma unroll
        for (int j = 0; j < NB; j++)
            hout_s[j * FD + f * D + lane] = acc[j];
    }
    __syncthreads();

    // ---------------- Stage 2: aggr[j][f][d] = sum_g g[j][f][g] * hout[j][g][d] ----------------
    // warp = batch j; lane = d; f processed in chunks of 8.
    {
        const int j = warp;
        const float* hout_j = hout_s + j * FD;
        const float* g_j    = g_s + j * FF;
        float*       aggr_j = h_s + j * FD;   // overwrite h (consumed)
        #pragma unroll
        for (int c = 0; c < 5; c++) {
            const int f0 = c * 8;
            float acc[8];
            #pragma unroll
            for (int i = 0; i < 8; i++) acc[i] = 0.0f;
            #pragma unroll 8
            for (int gi = 0; gi < F; gi++) {
                const float ho = hout_j[gi * D + lane];
                const float4 ga = *(const float4*)&g_j[gi * F + f0];
                const float4 gb = *(const float4*)&g_j[gi * F + f0 + 4];
                acc[0] += ga.x * ho;  acc[1] += ga.y * ho;
                acc[2] += ga.z * ho;  acc[3] += ga.w * ho;
                acc[4] += gb.x * ho;  acc[5] += gb.y * ho;
                acc[6] += gb.z * ho;  acc[7] += gb.w * ho;
            }
            #pragma unroll
            for (int i = 0; i < 8; i++)
                aggr_j[(f0 + i) * D + lane] = acc[i];
        }
    }
    __syncthreads();

    // ---------------- Stage 3: out[j][f][d] = sum_e W_in[f][d][e] * aggr[j][f][e] + bias[d] ----------------
    const float bias_v = __ldg(bias_p + lane);
    #pragma unroll
    for (int k = 0; k < 5; k++) {
        const int f = warp + k * 8;
        const float4* w4p = (const float4*)(W_in + (f * D + lane) * D);
        float acc[NB];
        #pragma unroll
        for (int j = 0; j < NB; j++) acc[j] = 0.0f;
        #pragma unroll
        for (int eq = 0; eq < D / 4; eq++) {
            const float4 w = __ldg(w4p + eq);
            #pragma unroll
            for (int j = 0; j < NB; j++) {
                const float4 av = *(const float4*)&h_s[j * FD + f * D + eq * 4];
                acc[j] += w.x * av.x + w.y * av.y + w.z * av.z + w.w * av.w;
            }
        }
        #pragma unroll
        for (int j = 0; j < NB; j++)
            out[(b0 + j) * FD + f * D + lane] = acc[j] + bias_v;
    }
}

extern "C" void kernel_launch(void* const* d_in, const int* in_sizes, int n_in,
                              void* d_out, int out_size)
{
    (void)in_sizes; (void)n_in; (void)out_size;
    const float* g     = (const float*)d_in[0];
    const float* h     = (const float*)d_in[1];
    const float* W_in  = (const float*)d_in[2];
    const float* W_out = (const float*)d_in[3];
    const float* bias  = (const float*)d_in[4];
    float* out = (float*)d_out;

    cudaFuncSetAttribute(graphlayer_kernel,
                         cudaFuncAttributeMaxDynamicSharedMemorySize, SMEM_BYTES);

    graphlayer_kernel<<<B_TOT / NB, 256, SMEM_BYTES>>>(g, h, W_in, W_out, bias, out);
}